// round 6
// baseline (speedup 1.0000x reference)
#include <cuda_runtime.h>

// ---------------------------------------------------------------------------
// GAT layer, folded + CSR softmax-aggregate, stream-overlapped:
//   stream A: edge feature dot (coalesced) + dst histogram   [no GEMM dep]
//   stream 0: z = feats_node @ Wn^T ; st[i]=(z.a_src, z.a_dst)
//   join ->  scan ; build (fuses logit = vdot + st[src].x + st[dst].y, lrelu,
//                          CSR scatter) ; warp-per-node softmax-aggregate
// ---------------------------------------------------------------------------

#define MAX_NODES 20000
#define MAX_EDGES 640000

__device__ __align__(16) float  g_z[MAX_NODES * 128];
__device__ __align__(8)  float2 g_st[MAX_NODES];
__device__ __align__(16) float  g_c[64];
__device__ float                g_vdot[MAX_EDGES];
__device__ int                  g_cnt[MAX_NODES];
__device__ int                  g_off[MAX_NODES];
__device__ int                  g_cur[MAX_NODES];
__device__ float                g_ecsr[MAX_EDGES];
__device__ int                  g_scsr[MAX_EDGES];

// -- prep: c = We^T a_e ; zero histogram --------------------------------------
__global__ void k_prep(const float* __restrict__ We,
                       const float* __restrict__ Wa, int n_nodes) {
    int t = blockIdx.x * blockDim.x + threadIdx.x;
    if (t < 64) {
        float acc = 0.f;
#pragma unroll 8
        for (int o = 0; o < 128; o++) acc += We[o * 64 + t] * Wa[256 + o];
        g_c[t] = acc;
    }
    if (t < n_nodes) g_cnt[t] = 0;
}

// -- edge feature dot, fully coalesced, 8 edges/warp + fused histogram --------
// lane loads fe4[w*128 + k*32 + lane] (contiguous 512B per LDG across warp).
// element (k*32+lane) belongs to edge 2k + (lane>>4), slice (lane&15).
__global__ __launch_bounds__(256) void k_edge_dot(const float4* __restrict__ fe4,
                                                  const int* __restrict__ dst,
                                                  int n_edges) {
    int w = (blockIdx.x * blockDim.x + threadIdx.x) >> 5;
    int lane = threadIdx.x & 31;
    if (w * 8 >= n_edges) return;
    int total4 = n_edges * 16;
    float4 cc = __ldg((const float4*)g_c + (lane & 15));
    float p[4];
#pragma unroll
    for (int k = 0; k < 4; k++) {
        int idx = w * 128 + k * 32 + lane;
        float4 v = (idx < total4) ? fe4[idx] : make_float4(0.f, 0.f, 0.f, 0.f);
        p[k] = v.x * cc.x + v.y * cc.y + v.z * cc.z + v.w * cc.w;
    }
#pragma unroll
    for (int o = 1; o < 16; o <<= 1) {
#pragma unroll
        for (int k = 0; k < 4; k++)
            p[k] += __shfl_xor_sync(0xFFFFFFFFu, p[k], o);
    }
    if ((lane & 15) == 0) {
        int g = lane >> 4;
#pragma unroll
        for (int k = 0; k < 4; k++) {
            int eid = w * 8 + 2 * k + g;
            if (eid < n_edges) {
                g_vdot[eid] = p[k];
                atomicAdd(&g_cnt[dst[eid]], 1);
            }
        }
    }
}

// -- z = A @ B^T, A [M,128], B [128,128], both K-contiguous -------------------
__global__ __launch_bounds__(256) void k_gemm(const float* __restrict__ A,
                                              const float* __restrict__ B,
                                              int M) {
    __shared__ float As[16][132];
    __shared__ float Bs[16][132];
    const int tid = threadIdx.x;
    const int blockRow = blockIdx.x * 128;
    const int tr = tid >> 4;
    const int tc = tid & 15;
    const int lrow = tid >> 2;
    const int lcol = (tid & 3) * 4;

    float acc[8][8];
#pragma unroll
    for (int i = 0; i < 8; i++)
#pragma unroll
        for (int j = 0; j < 8; j++) acc[i][j] = 0.f;

    for (int kt = 0; kt < 128; kt += 16) {
#pragma unroll
        for (int h = 0; h < 2; h++) {
            int m = lrow + h * 64;
            int gm = blockRow + m;
            float4 v = (gm < M)
                           ? *(const float4*)&A[(size_t)gm * 128 + kt + lcol]
                           : make_float4(0.f, 0.f, 0.f, 0.f);
            As[lcol + 0][m] = v.x; As[lcol + 1][m] = v.y;
            As[lcol + 2][m] = v.z; As[lcol + 3][m] = v.w;
        }
#pragma unroll
        for (int h = 0; h < 2; h++) {
            int n = lrow + h * 64;
            float4 v = *(const float4*)&B[(size_t)n * 128 + kt + lcol];
            Bs[lcol + 0][n] = v.x; Bs[lcol + 1][n] = v.y;
            Bs[lcol + 2][n] = v.z; Bs[lcol + 3][n] = v.w;
        }
        __syncthreads();
#pragma unroll
        for (int k = 0; k < 16; k++) {
            float ra[8], rb[8];
#pragma unroll
            for (int i = 0; i < 8; i++) ra[i] = As[k][tr * 8 + i];
#pragma unroll
            for (int j = 0; j < 8; j++) rb[j] = Bs[k][tc * 8 + j];
#pragma unroll
            for (int i = 0; i < 8; i++)
#pragma unroll
                for (int j = 0; j < 8; j++) acc[i][j] += ra[i] * rb[j];
        }
        __syncthreads();
    }
#pragma unroll
    for (int i = 0; i < 8; i++) {
        int gm = blockRow + tr * 8 + i;
        if (gm < M) {
            float* out = &g_z[(size_t)gm * 128 + tc * 8];
            *(float4*)(out + 0) = make_float4(acc[i][0], acc[i][1], acc[i][2], acc[i][3]);
            *(float4*)(out + 4) = make_float4(acc[i][4], acc[i][5], acc[i][6], acc[i][7]);
        }
    }
}

// -- per-node (s,t) dots: warp per node, packed float2 ------------------------
__global__ void k_nodedot(const float* __restrict__ Wa, int n_nodes) {
    int gw = (blockIdx.x * blockDim.x + threadIdx.x) >> 5;
    int lane = threadIdx.x & 31;
    if (gw >= n_nodes) return;
    float4 z4 = ((const float4*)g_z)[(size_t)gw * 32 + lane];
    float4 a4 = ((const float4*)Wa)[lane];
    float4 b4 = ((const float4*)(Wa + 128))[lane];
    float s = z4.x * a4.x + z4.y * a4.y + z4.z * a4.z + z4.w * a4.w;
    float t = z4.x * b4.x + z4.y * b4.y + z4.z * b4.z + z4.w * b4.w;
#pragma unroll
    for (int o = 16; o > 0; o >>= 1) {
        s += __shfl_xor_sync(0xFFFFFFFFu, s, o);
        t += __shfl_xor_sync(0xFFFFFFFFu, t, o);
    }
    if (lane == 0) g_st[gw] = make_float2(s, t);
}

// -- exclusive scan of g_cnt -> g_off, g_cur (single block) -------------------
__global__ __launch_bounds__(1024) void k_scan(int n) {
    __shared__ int wsum[32];
    int tid = threadIdx.x;
    int lane = tid & 31, wid = tid >> 5;
    int C = (n + 1023) >> 10;
    int lo = tid * C;
    int hi = lo + C; if (hi > n) hi = n; if (lo > n) lo = n;
    int local = 0;
    for (int i = lo; i < hi; i++) local += g_cnt[i];
    int v = local;
#pragma unroll
    for (int o = 1; o < 32; o <<= 1) {
        int u = __shfl_up_sync(0xFFFFFFFFu, v, o);
        if (lane >= o) v += u;
    }
    if (lane == 31) wsum[wid] = v;
    __syncthreads();
    if (wid == 0) {
        int wv = wsum[lane];
#pragma unroll
        for (int o = 1; o < 32; o <<= 1) {
            int u = __shfl_up_sync(0xFFFFFFFFu, wv, o);
            if (lane >= o) wv += u;
        }
        wsum[lane] = wv;
    }
    __syncthreads();
    int run = v - local + (wid > 0 ? wsum[wid - 1] : 0);
    for (int i = lo; i < hi; i++) {
        g_off[i] = run;
        g_cur[i] = run;
        run += g_cnt[i];
    }
}

// -- build CSR-ordered e / src arrays, fused logit + leaky-relu ----------------
__global__ void k_build(const int* __restrict__ src,
                        const int* __restrict__ dst, int n_edges) {
    int i = blockIdx.x * blockDim.x + threadIdx.x;
    if (i >= n_edges) return;
    int d = dst[i];
    int s = src[i];
    float logit = g_vdot[i] + g_st[s].x + g_st[d].y;
    float e = (logit > 0.f) ? logit : 0.2f * logit;
    int pos = atomicAdd(&g_cur[d], 1);
    g_ecsr[pos] = e;
    g_scsr[pos] = s;
}

// -- warp per node: softmax + weighted aggregate, unroll x4 --------------------
__global__ __launch_bounds__(256) void k_aggregate(float* __restrict__ h,
                                                   int n_nodes) {
    int node = (blockIdx.x * blockDim.x + threadIdx.x) >> 5;
    int lane = threadIdx.x & 31;
    if (node >= n_nodes) return;
    int off = g_off[node];
    int deg = g_cnt[node];

    float m = -3.402823466e+38f;
    for (int j = lane; j < deg; j += 32) m = fmaxf(m, g_ecsr[off + j]);
#pragma unroll
    for (int o = 16; o > 0; o >>= 1)
        m = fmaxf(m, __shfl_xor_sync(0xFFFFFFFFu, m, o));

    float S = 0.f;
    for (int j = lane; j < deg; j += 32) S += __expf(g_ecsr[off + j] - m);
#pragma unroll
    for (int o = 16; o > 0; o >>= 1) S += __shfl_xor_sync(0xFFFFFFFFu, S, o);
    float rS = (deg > 0) ? (1.f / S) : 0.f;

    float4 acc = make_float4(0.f, 0.f, 0.f, 0.f);
    int j = 0;
    for (; j + 4 <= deg; j += 4) {
        float e0 = g_ecsr[off + j + 0], e1 = g_ecsr[off + j + 1];
        float e2 = g_ecsr[off + j + 2], e3 = g_ecsr[off + j + 3];
        int   s0 = g_scsr[off + j + 0], s1 = g_scsr[off + j + 1];
        int   s2 = g_scsr[off + j + 2], s3 = g_scsr[off + j + 3];
        float4 z0 = *(const float4*)&g_z[(size_t)s0 * 128 + lane * 4];
        float4 z1 = *(const float4*)&g_z[(size_t)s1 * 128 + lane * 4];
        float4 z2 = *(const float4*)&g_z[(size_t)s2 * 128 + lane * 4];
        float4 z3 = *(const float4*)&g_z[(size_t)s3 * 128 + lane * 4];
        float a0 = __expf(e0 - m) * rS;
        float a1 = __expf(e1 - m) * rS;
        float a2 = __expf(e2 - m) * rS;
        float a3 = __expf(e3 - m) * rS;
        acc.x += a0 * z0.x + a1 * z1.x + a2 * z2.x + a3 * z3.x;
        acc.y += a0 * z0.y + a1 * z1.y + a2 * z2.y + a3 * z3.y;
        acc.z += a0 * z0.z + a1 * z1.z + a2 * z2.z + a3 * z3.z;
        acc.w += a0 * z0.w + a1 * z1.w + a2 * z2.w + a3 * z3.w;
    }
    for (; j < deg; j++) {
        float e0 = g_ecsr[off + j];
        int   s0 = g_scsr[off + j];
        float4 z0 = *(const float4*)&g_z[(size_t)s0 * 128 + lane * 4];
        float a0 = __expf(e0 - m) * rS;
        acc.x += a0 * z0.x; acc.y += a0 * z0.y;
        acc.z += a0 * z0.z; acc.w += a0 * z0.w;
    }
    *(float4*)&h[(size_t)node * 128 + lane * 4] = acc;
}

extern "C" void kernel_launch(void* const* d_in, const int* in_sizes, int n_in,
                              void* d_out, int out_size) {
    const float* feats_node = (const float*)d_in[0];
    const float* feats_edge = (const float*)d_in[1];
    const float* Wn         = (const float*)d_in[2];
    const float* We         = (const float*)d_in[3];
    const float* Wa         = (const float*)d_in[4];
    const int*   src        = (const int*)d_in[5];
    const int*   dst        = (const int*)d_in[6];
    float*       h          = (float*)d_out;

    int n_nodes = in_sizes[0] / 128;
    int n_edges = in_sizes[5];

    // Side stream + events: created once (outside capture, on the correctness
    // call), then used identically every call. No device memory involved.
    static cudaStream_t s2 = nullptr;
    static cudaEvent_t evFork = nullptr, evJoin = nullptr;
    if (s2 == nullptr) {
        cudaStreamCreateWithFlags(&s2, cudaStreamNonBlocking);
        cudaEventCreateWithFlags(&evFork, cudaEventDisableTiming);
        cudaEventCreateWithFlags(&evJoin, cudaEventDisableTiming);
    }

    k_prep<<<(n_nodes + 255) / 256, 256>>>(We, Wa, n_nodes);

    // fork: edge dot (no GEMM dependency) runs concurrently with gemm+nodedot
    cudaEventRecord(evFork, 0);
    cudaStreamWaitEvent(s2, evFork, 0);
    int warps_ed = (n_edges + 7) / 8;
    k_edge_dot<<<(warps_ed + 7) / 8, 256, 0, s2>>>((const float4*)feats_edge,
                                                   dst, n_edges);

    k_gemm<<<(n_nodes + 127) / 128, 256>>>(feats_node, Wn, n_nodes);
    k_nodedot<<<(n_nodes + 7) / 8, 256>>>(Wa, n_nodes);

    // join
    cudaEventRecord(evJoin, s2);
    cudaStreamWaitEvent(0, evJoin, 0);

    k_scan<<<1, 1024>>>(n_nodes);
    k_build<<<(n_edges + 255) / 256, 256>>>(src, dst, n_edges);
    k_aggregate<<<(n_nodes + 7) / 8, 256>>>(h, n_nodes);
}

// round 7
// speedup vs baseline: 1.3045x; 1.3045x over previous
#include <cuda_runtime.h>

// ---------------------------------------------------------------------------
// GAT layer, folded + CSR softmax-aggregate (single stream):
//   c      = We^T @ a_e                       (edge GEMM eliminated)
//   edge_dot: vdot_k = feats_edge[k].c  (fully coalesced) + dst histogram
//   gemm   : z = feats_node @ Wn^T  with fused epilogue st[i]=(z.a_src,z.a_dst)
//   scan   : CSR offsets
//   build  : e = lrelu(vdot + st[src].x + st[dst].y), scatter packed (e,src)
//   aggregate: warp-per-node max / sum-exp / h = sum alpha*z[src] (L2 gather)
// ---------------------------------------------------------------------------

#define MAX_NODES 20000
#define MAX_EDGES 640000

__device__ __align__(16) float  g_z[MAX_NODES * 128];
__device__ __align__(8)  float2 g_st[MAX_NODES];
__device__ __align__(16) float  g_c[64];
__device__ float                g_vdot[MAX_EDGES];
__device__ int                  g_cnt[MAX_NODES];
__device__ int                  g_off[MAX_NODES];
__device__ int                  g_cur[MAX_NODES];
__device__ __align__(8) float2  g_pcsr[MAX_EDGES];   // (e, src-as-float-bits)

// -- prep: c = We^T a_e ; zero histogram --------------------------------------
__global__ void k_prep(const float* __restrict__ We,
                       const float* __restrict__ Wa, int n_nodes) {
    int t = blockIdx.x * blockDim.x + threadIdx.x;
    if (t < 64) {
        float acc = 0.f;
#pragma unroll 8
        for (int o = 0; o < 128; o++) acc += We[o * 64 + t] * Wa[256 + o];
        g_c[t] = acc;
    }
    if (t < n_nodes) g_cnt[t] = 0;
}

// -- edge feature dot, fully coalesced, 8 edges/warp + fused histogram --------
__global__ __launch_bounds__(256) void k_edge_dot(const float4* __restrict__ fe4,
                                                  const int* __restrict__ dst,
                                                  int n_edges) {
    int w = (blockIdx.x * blockDim.x + threadIdx.x) >> 5;
    int lane = threadIdx.x & 31;
    if (w * 8 >= n_edges) return;
    int total4 = n_edges * 16;
    float4 cc = __ldg((const float4*)g_c + (lane & 15));
    float p[4];
#pragma unroll
    for (int k = 0; k < 4; k++) {
        int idx = w * 128 + k * 32 + lane;
        float4 v = (idx < total4) ? fe4[idx] : make_float4(0.f, 0.f, 0.f, 0.f);
        p[k] = v.x * cc.x + v.y * cc.y + v.z * cc.z + v.w * cc.w;
    }
#pragma unroll
    for (int o = 1; o < 16; o <<= 1) {
#pragma unroll
        for (int k = 0; k < 4; k++)
            p[k] += __shfl_xor_sync(0xFFFFFFFFu, p[k], o);
    }
    if ((lane & 15) == 0) {
        int g = lane >> 4;
#pragma unroll
        for (int k = 0; k < 4; k++) {
            int eid = w * 8 + 2 * k + g;
            if (eid < n_edges) {
                g_vdot[eid] = p[k];
                atomicAdd(&g_cnt[dst[eid]], 1);
            }
        }
    }
}

// -- z = A @ B^T with fused (s,t) epilogue ------------------------------------
// thread (tr,tc) holds acc[i][j] = z[row=blk+tr*8+i][col=tc*8+j]; the 16
// same-tr lanes (contiguous half-warp) cover all 128 cols -> 4-shfl reduce.
__global__ __launch_bounds__(256) void k_gemm(const float* __restrict__ A,
                                              const float* __restrict__ B,
                                              const float* __restrict__ Wa,
                                              int M) {
    __shared__ float As[16][132];
    __shared__ float Bs[16][132];
    const int tid = threadIdx.x;
    const int blockRow = blockIdx.x * 128;
    const int tr = tid >> 4;
    const int tc = tid & 15;
    const int lrow = tid >> 2;
    const int lcol = (tid & 3) * 4;

    float acc[8][8];
#pragma unroll
    for (int i = 0; i < 8; i++)
#pragma unroll
        for (int j = 0; j < 8; j++) acc[i][j] = 0.f;

    for (int kt = 0; kt < 128; kt += 16) {
#pragma unroll
        for (int h = 0; h < 2; h++) {
            int m = lrow + h * 64;
            int gm = blockRow + m;
            float4 v = (gm < M)
                           ? *(const float4*)&A[(size_t)gm * 128 + kt + lcol]
                           : make_float4(0.f, 0.f, 0.f, 0.f);
            As[lcol + 0][m] = v.x; As[lcol + 1][m] = v.y;
            As[lcol + 2][m] = v.z; As[lcol + 3][m] = v.w;
        }
#pragma unroll
        for (int h = 0; h < 2; h++) {
            int n = lrow + h * 64;
            float4 v = *(const float4*)&B[(size_t)n * 128 + kt + lcol];
            Bs[lcol + 0][n] = v.x; Bs[lcol + 1][n] = v.y;
            Bs[lcol + 2][n] = v.z; Bs[lcol + 3][n] = v.w;
        }
        __syncthreads();
#pragma unroll
        for (int k = 0; k < 16; k++) {
            float ra[8], rb[8];
#pragma unroll
            for (int i = 0; i < 8; i++) ra[i] = As[k][tr * 8 + i];
#pragma unroll
            for (int j = 0; j < 8; j++) rb[j] = Bs[k][tc * 8 + j];
#pragma unroll
            for (int i = 0; i < 8; i++)
#pragma unroll
                for (int j = 0; j < 8; j++) acc[i][j] += ra[i] * rb[j];
        }
        __syncthreads();
    }

    // store z tile
#pragma unroll
    for (int i = 0; i < 8; i++) {
        int gm = blockRow + tr * 8 + i;
        if (gm < M) {
            float* out = &g_z[(size_t)gm * 128 + tc * 8];
            *(float4*)(out + 0) = make_float4(acc[i][0], acc[i][1], acc[i][2], acc[i][3]);
            *(float4*)(out + 4) = make_float4(acc[i][4], acc[i][5], acc[i][6], acc[i][7]);
        }
    }

    // fused epilogue: per-row dots with a_src / a_dst
    float asv[8], adv[8];
#pragma unroll
    for (int j = 0; j < 8; j++) {
        asv[j] = __ldg(Wa + tc * 8 + j);         // a_src
        adv[j] = __ldg(Wa + 128 + tc * 8 + j);   // a_dst
    }
#pragma unroll
    for (int i = 0; i < 8; i++) {
        float s = 0.f, t = 0.f;
#pragma unroll
        for (int j = 0; j < 8; j++) {
            s += acc[i][j] * asv[j];
            t += acc[i][j] * adv[j];
        }
#pragma unroll
        for (int o = 1; o < 16; o <<= 1) {
            s += __shfl_xor_sync(0xFFFFFFFFu, s, o);
            t += __shfl_xor_sync(0xFFFFFFFFu, t, o);
        }
        int gm = blockRow + tr * 8 + i;
        if (tc == 0 && gm < M) g_st[gm] = make_float2(s, t);
    }
}

// -- exclusive scan of g_cnt -> g_off, g_cur (single block) -------------------
__global__ __launch_bounds__(1024) void k_scan(int n) {
    __shared__ int wsum[32];
    int tid = threadIdx.x;
    int lane = tid & 31, wid = tid >> 5;
    int C = (n + 1023) >> 10;
    int lo = tid * C;
    int hi = lo + C; if (hi > n) hi = n; if (lo > n) lo = n;
    int local = 0;
    for (int i = lo; i < hi; i++) local += g_cnt[i];
    int v = local;
#pragma unroll
    for (int o = 1; o < 32; o <<= 1) {
        int u = __shfl_up_sync(0xFFFFFFFFu, v, o);
        if (lane >= o) v += u;
    }
    if (lane == 31) wsum[wid] = v;
    __syncthreads();
    if (wid == 0) {
        int wv = wsum[lane];
#pragma unroll
        for (int o = 1; o < 32; o <<= 1) {
            int u = __shfl_up_sync(0xFFFFFFFFu, wv, o);
            if (lane >= o) wv += u;
        }
        wsum[lane] = wv;
    }
    __syncthreads();
    int run = v - local + (wid > 0 ? wsum[wid - 1] : 0);
    for (int i = lo; i < hi; i++) {
        g_off[i] = run;
        g_cur[i] = run;
        run += g_cnt[i];
    }
}

// -- build CSR-ordered packed (e, src), fused logit + leaky-relu ---------------
__global__ void k_build(const int* __restrict__ src,
                        const int* __restrict__ dst, int n_edges) {
    int i = blockIdx.x * blockDim.x + threadIdx.x;
    if (i >= n_edges) return;
    int d = dst[i];
    int s = src[i];
    float logit = g_vdot[i] + g_st[s].x + g_st[d].y;
    float e = (logit > 0.f) ? logit : 0.2f * logit;
    int pos = atomicAdd(&g_cur[d], 1);
    g_pcsr[pos] = make_float2(e, __int_as_float(s));
}

// -- warp per node: softmax + weighted aggregate, unroll x4 --------------------
__global__ __launch_bounds__(256) void k_aggregate(float* __restrict__ h,
                                                   int n_nodes) {
    int node = (blockIdx.x * blockDim.x + threadIdx.x) >> 5;
    int lane = threadIdx.x & 31;
    if (node >= n_nodes) return;
    int off = g_off[node];
    int deg = g_cnt[node];

    float m = -3.402823466e+38f;
    for (int j = lane; j < deg; j += 32) m = fmaxf(m, g_pcsr[off + j].x);
#pragma unroll
    for (int o = 16; o > 0; o >>= 1)
        m = fmaxf(m, __shfl_xor_sync(0xFFFFFFFFu, m, o));

    float S = 0.f;
    for (int j = lane; j < deg; j += 32) S += __expf(g_pcsr[off + j].x - m);
#pragma unroll
    for (int o = 16; o > 0; o >>= 1) S += __shfl_xor_sync(0xFFFFFFFFu, S, o);
    float rS = (deg > 0) ? (1.f / S) : 0.f;

    float4 acc = make_float4(0.f, 0.f, 0.f, 0.f);
    int j = 0;
    for (; j + 4 <= deg; j += 4) {
        float2 p0 = g_pcsr[off + j + 0], p1 = g_pcsr[off + j + 1];
        float2 p2 = g_pcsr[off + j + 2], p3 = g_pcsr[off + j + 3];
        int s0 = __float_as_int(p0.y), s1 = __float_as_int(p1.y);
        int s2 = __float_as_int(p2.y), s3 = __float_as_int(p3.y);
        float4 z0 = *(const float4*)&g_z[(size_t)s0 * 128 + lane * 4];
        float4 z1 = *(const float4*)&g_z[(size_t)s1 * 128 + lane * 4];
        float4 z2 = *(const float4*)&g_z[(size_t)s2 * 128 + lane * 4];
        float4 z3 = *(const float4*)&g_z[(size_t)s3 * 128 + lane * 4];
        float a0 = __expf(p0.x - m) * rS;
        float a1 = __expf(p1.x - m) * rS;
        float a2 = __expf(p2.x - m) * rS;
        float a3 = __expf(p3.x - m) * rS;
        acc.x += a0 * z0.x + a1 * z1.x + a2 * z2.x + a3 * z3.x;
        acc.y += a0 * z0.y + a1 * z1.y + a2 * z2.y + a3 * z3.y;
        acc.z += a0 * z0.z + a1 * z1.z + a2 * z2.z + a3 * z3.z;
        acc.w += a0 * z0.w + a1 * z1.w + a2 * z2.w + a3 * z3.w;
    }
    for (; j < deg; j++) {
        float2 p0 = g_pcsr[off + j];
        int s0 = __float_as_int(p0.y);
        float4 z0 = *(const float4*)&g_z[(size_t)s0 * 128 + lane * 4];
        float a0 = __expf(p0.x - m) * rS;
        acc.x += a0 * z0.x; acc.y += a0 * z0.y;
        acc.z += a0 * z0.z; acc.w += a0 * z0.w;
    }
    *(float4*)&h[(size_t)node * 128 + lane * 4] = acc;
}

extern "C" void kernel_launch(void* const* d_in, const int* in_sizes, int n_in,
                              void* d_out, int out_size) {
    const float* feats_node = (const float*)d_in[0];
    const float* feats_edge = (const float*)d_in[1];
    const float* Wn         = (const float*)d_in[2];
    const float* We         = (const float*)d_in[3];
    const float* Wa         = (const float*)d_in[4];
    const int*   src        = (const int*)d_in[5];
    const int*   dst        = (const int*)d_in[6];
    float*       h          = (float*)d_out;

    int n_nodes = in_sizes[0] / 128;
    int n_edges = in_sizes[5];

    k_prep<<<(n_nodes + 255) / 256, 256>>>(We, Wa, n_nodes);
    int warps_ed = (n_edges + 7) / 8;
    k_edge_dot<<<(warps_ed + 7) / 8, 256>>>((const float4*)feats_edge, dst,
                                            n_edges);
    k_gemm<<<(n_nodes + 127) / 128, 256>>>(feats_node, Wn, Wa, n_nodes);
    k_scan<<<1, 1024>>>(n_nodes);
    k_build<<<(n_edges + 255) / 256, 256>>>(src, dst, n_edges);
    k_aggregate<<<(n_nodes + 7) / 8, 256>>>(h, n_nodes);
}

// round 8
// speedup vs baseline: 1.4274x; 1.0942x over previous
#include <cuda_runtime.h>

// ---------------------------------------------------------------------------
// GAT layer, folded + CSR softmax-aggregate (single stream):
//   c      = We^T @ a_e                       (edge GEMM eliminated)
//   edge_dot: vdot_k = feats_edge[k].c  (fully coalesced) + dst histogram
//   gemm   : z = feats_node @ Wn^T  with fused epilogue st[i]=(z.a_src,z.a_dst)
//   scan   : CSR offsets (register-resident, int4 I/O)
//   build  : e = lrelu(vdot + st[src].x + st[dst].y), scatter packed (e,src)
//   aggregate: warp-per-node max / sum-exp / h = sum alpha*z[src] (L2 gather)
// ---------------------------------------------------------------------------

#define MAX_NODES 20000
#define MAX_EDGES 640000

__device__ __align__(16) float  g_z[MAX_NODES * 128];
__device__ __align__(8)  float2 g_st[MAX_NODES];
__device__ __align__(16) float  g_c[64];
__device__ float                g_vdot[MAX_EDGES];
__device__ __align__(16) int    g_cnt[MAX_NODES];
__device__ __align__(16) int    g_off[MAX_NODES];
__device__ __align__(16) int    g_cur[MAX_NODES];
__device__ __align__(8) float2  g_pcsr[MAX_EDGES];   // (e, src-as-float-bits)

// -- prep: c = We^T a_e ; zero histogram --------------------------------------
__global__ void k_prep(const float* __restrict__ We,
                       const float* __restrict__ Wa, int n_nodes) {
    int t = blockIdx.x * blockDim.x + threadIdx.x;
    if (t < 64) {
        float acc = 0.f;
#pragma unroll 8
        for (int o = 0; o < 128; o++) acc += We[o * 64 + t] * Wa[256 + o];
        g_c[t] = acc;
    }
    if (t < n_nodes) g_cnt[t] = 0;
}

// -- edge feature dot, fully coalesced, 8 edges/warp + fused histogram --------
__global__ __launch_bounds__(256) void k_edge_dot(const float4* __restrict__ fe4,
                                                  const int* __restrict__ dst,
                                                  int n_edges) {
    int w = (blockIdx.x * blockDim.x + threadIdx.x) >> 5;
    int lane = threadIdx.x & 31;
    if (w * 8 >= n_edges) return;
    int total4 = n_edges * 16;
    float4 cc = __ldg((const float4*)g_c + (lane & 15));
    float p[4];
#pragma unroll
    for (int k = 0; k < 4; k++) {
        int idx = w * 128 + k * 32 + lane;
        float4 v = (idx < total4) ? fe4[idx] : make_float4(0.f, 0.f, 0.f, 0.f);
        p[k] = v.x * cc.x + v.y * cc.y + v.z * cc.z + v.w * cc.w;
    }
#pragma unroll
    for (int o = 1; o < 16; o <<= 1) {
#pragma unroll
        for (int k = 0; k < 4; k++)
            p[k] += __shfl_xor_sync(0xFFFFFFFFu, p[k], o);
    }
    if ((lane & 15) == 0) {
        int g = lane >> 4;
#pragma unroll
        for (int k = 0; k < 4; k++) {
            int eid = w * 8 + 2 * k + g;
            if (eid < n_edges) {
                g_vdot[eid] = p[k];
                atomicAdd(&g_cnt[dst[eid]], 1);
            }
        }
    }
}

// -- z = A @ B^T with fused (s,t) epilogue ------------------------------------
__global__ __launch_bounds__(256) void k_gemm(const float* __restrict__ A,
                                              const float* __restrict__ B,
                                              const float* __restrict__ Wa,
                                              int M) {
    __shared__ float As[16][132];
    __shared__ float Bs[16][132];
    const int tid = threadIdx.x;
    const int blockRow = blockIdx.x * 128;
    const int tr = tid >> 4;
    const int tc = tid & 15;
    const int lrow = tid >> 2;
    const int lcol = (tid & 3) * 4;

    float acc[8][8];
#pragma unroll
    for (int i = 0; i < 8; i++)
#pragma unroll
        for (int j = 0; j < 8; j++) acc[i][j] = 0.f;

    for (int kt = 0; kt < 128; kt += 16) {
#pragma unroll
        for (int h = 0; h < 2; h++) {
            int m = lrow + h * 64;
            int gm = blockRow + m;
            float4 v = (gm < M)
                           ? *(const float4*)&A[(size_t)gm * 128 + kt + lcol]
                           : make_float4(0.f, 0.f, 0.f, 0.f);
            As[lcol + 0][m] = v.x; As[lcol + 1][m] = v.y;
            As[lcol + 2][m] = v.z; As[lcol + 3][m] = v.w;
        }
#pragma unroll
        for (int h = 0; h < 2; h++) {
            int n = lrow + h * 64;
            float4 v = *(const float4*)&B[(size_t)n * 128 + kt + lcol];
            Bs[lcol + 0][n] = v.x; Bs[lcol + 1][n] = v.y;
            Bs[lcol + 2][n] = v.z; Bs[lcol + 3][n] = v.w;
        }
        __syncthreads();
#pragma unroll
        for (int k = 0; k < 16; k++) {
            float ra[8], rb[8];
#pragma unroll
            for (int i = 0; i < 8; i++) ra[i] = As[k][tr * 8 + i];
#pragma unroll
            for (int j = 0; j < 8; j++) rb[j] = Bs[k][tc * 8 + j];
#pragma unroll
            for (int i = 0; i < 8; i++)
#pragma unroll
                for (int j = 0; j < 8; j++) acc[i][j] += ra[i] * rb[j];
        }
        __syncthreads();
    }

#pragma unroll
    for (int i = 0; i < 8; i++) {
        int gm = blockRow + tr * 8 + i;
        if (gm < M) {
            float* out = &g_z[(size_t)gm * 128 + tc * 8];
            *(float4*)(out + 0) = make_float4(acc[i][0], acc[i][1], acc[i][2], acc[i][3]);
            *(float4*)(out + 4) = make_float4(acc[i][4], acc[i][5], acc[i][6], acc[i][7]);
        }
    }

    float asv[8], adv[8];
#pragma unroll
    for (int j = 0; j < 8; j++) {
        asv[j] = __ldg(Wa + tc * 8 + j);
        adv[j] = __ldg(Wa + 128 + tc * 8 + j);
    }
#pragma unroll
    for (int i = 0; i < 8; i++) {
        float s = 0.f, t = 0.f;
#pragma unroll
        for (int j = 0; j < 8; j++) {
            s += acc[i][j] * asv[j];
            t += acc[i][j] * adv[j];
        }
#pragma unroll
        for (int o = 1; o < 16; o <<= 1) {
            s += __shfl_xor_sync(0xFFFFFFFFu, s, o);
            t += __shfl_xor_sync(0xFFFFFFFFu, t, o);
        }
        int gm = blockRow + tr * 8 + i;
        if (tc == 0 && gm < M) g_st[gm] = make_float2(s, t);
    }
}

// -- exclusive scan: register-resident, int4 loads/stores, MLP=5 ---------------
__global__ __launch_bounds__(1024) void k_scan(int n) {
    __shared__ int wsum[32];
    int tid = threadIdx.x;
    int lane = tid & 31, wid = tid >> 5;
    const int C = (n + 1023) >> 10;          // <= 20 for MAX_NODES
    int lo = tid * C;
    int cnt = n - lo; if (cnt < 0) cnt = 0; if (cnt > C) cnt = C;

    int vals[20];
    bool fast = (cnt == C) && ((C & 3) == 0) && ((lo & 3) == 0);
    if (fast) {
#pragma unroll
        for (int k = 0; k < 5; k++) {
            if (k * 4 < C) {
                int4 v = *(const int4*)&g_cnt[lo + k * 4];
                vals[k * 4 + 0] = v.x; vals[k * 4 + 1] = v.y;
                vals[k * 4 + 2] = v.z; vals[k * 4 + 3] = v.w;
            }
        }
    } else {
        for (int i = 0; i < cnt; i++) vals[i] = g_cnt[lo + i];
    }

    int local = 0;
    for (int i = 0; i < cnt; i++) local += vals[i];

    int v = local;
#pragma unroll
    for (int o = 1; o < 32; o <<= 1) {
        int u = __shfl_up_sync(0xFFFFFFFFu, v, o);
        if (lane >= o) v += u;
    }
    if (lane == 31) wsum[wid] = v;
    __syncthreads();
    if (wid == 0) {
        int wv = wsum[lane];
#pragma unroll
        for (int o = 1; o < 32; o <<= 1) {
            int u = __shfl_up_sync(0xFFFFFFFFu, wv, o);
            if (lane >= o) wv += u;
        }
        wsum[lane] = wv;
    }
    __syncthreads();
    int run = v - local + (wid > 0 ? wsum[wid - 1] : 0);

    // prefix in registers, then vector stores
    int pref[20];
    for (int i = 0; i < cnt; i++) { pref[i] = run; run += vals[i]; }
    if (fast) {
#pragma unroll
        for (int k = 0; k < 5; k++) {
            if (k * 4 < C) {
                int4 pv = make_int4(pref[k * 4 + 0], pref[k * 4 + 1],
                                    pref[k * 4 + 2], pref[k * 4 + 3]);
                *(int4*)&g_off[lo + k * 4] = pv;
                *(int4*)&g_cur[lo + k * 4] = pv;
            }
        }
    } else {
        for (int i = 0; i < cnt; i++) {
            g_off[lo + i] = pref[i];
            g_cur[lo + i] = pref[i];
        }
    }
}

// -- build CSR-ordered packed (e, src), fused logit + leaky-relu ---------------
__global__ void k_build(const int* __restrict__ src,
                        const int* __restrict__ dst, int n_edges) {
    int i = blockIdx.x * blockDim.x + threadIdx.x;
    if (i >= n_edges) return;
    int d = dst[i];
    int s = src[i];
    float logit = g_vdot[i] + g_st[s].x + g_st[d].y;
    float e = (logit > 0.f) ? logit : 0.2f * logit;
    int pos = atomicAdd(&g_cur[d], 1);
    g_pcsr[pos] = make_float2(e, __int_as_float(s));
}

// -- warp per node: softmax + weighted aggregate, MLP x8 -----------------------
__global__ __launch_bounds__(256) void k_aggregate(float* __restrict__ h,
                                                   int n_nodes) {
    int node = (blockIdx.x * blockDim.x + threadIdx.x) >> 5;
    int lane = threadIdx.x & 31;
    if (node >= n_nodes) return;
    int off = g_off[node];
    int deg = g_cnt[node];

    float m = -3.402823466e+38f;
    for (int j = lane; j < deg; j += 32) m = fmaxf(m, g_pcsr[off + j].x);
#pragma unroll
    for (int o = 16; o > 0; o >>= 1)
        m = fmaxf(m, __shfl_xor_sync(0xFFFFFFFFu, m, o));

    float S = 0.f;
    for (int j = lane; j < deg; j += 32) S += __expf(g_pcsr[off + j].x - m);
#pragma unroll
    for (int o = 16; o > 0; o >>= 1) S += __shfl_xor_sync(0xFFFFFFFFu, S, o);
    float rS = (deg > 0) ? (1.f / S) : 0.f;

    float4 accA = make_float4(0.f, 0.f, 0.f, 0.f);
    float4 accB = make_float4(0.f, 0.f, 0.f, 0.f);
    int j = 0;
    for (; j + 8 <= deg; j += 8) {
        float2 p[8];
        const float4* zp[8];
#pragma unroll
        for (int q = 0; q < 8; q++) {
            p[q] = g_pcsr[off + j + q];
            zp[q] = (const float4*)&g_z[(size_t)__float_as_int(p[q].y) * 128 +
                                        lane * 4];
        }
        float4 z[8];
#pragma unroll
        for (int q = 0; q < 8; q++) z[q] = *zp[q];
#pragma unroll
        for (int q = 0; q < 8; q++) {
            float a = __expf(p[q].x - m) * rS;
            float4* acc = (q & 1) ? &accB : &accA;
            acc->x += a * z[q].x; acc->y += a * z[q].y;
            acc->z += a * z[q].z; acc->w += a * z[q].w;
        }
    }
    for (; j < deg; j++) {
        float2 p0 = g_pcsr[off + j];
        int s0 = __float_as_int(p0.y);
        float4 z0 = *(const float4*)&g_z[(size_t)s0 * 128 + lane * 4];
        float a0 = __expf(p0.x - m) * rS;
        accA.x += a0 * z0.x; accA.y += a0 * z0.y;
        accA.z += a0 * z0.z; accA.w += a0 * z0.w;
    }
    accA.x += accB.x; accA.y += accB.y; accA.z += accB.z; accA.w += accB.w;
    *(float4*)&h[(size_t)node * 128 + lane * 4] = accA;
}

extern "C" void kernel_launch(void* const* d_in, const int* in_sizes, int n_in,
                              void* d_out, int out_size) {
    const float* feats_node = (const float*)d_in[0];
    const float* feats_edge = (const float*)d_in[1];
    const float* Wn         = (const float*)d_in[2];
    const float* We         = (const float*)d_in[3];
    const float* Wa         = (const float*)d_in[4];
    const int*   src        = (const int*)d_in[5];
    const int*   dst        = (const int*)d_in[6];
    float*       h          = (float*)d_out;

    int n_nodes = in_sizes[0] / 128;
    int n_edges = in_sizes[5];

    k_prep<<<(n_nodes + 255) / 256, 256>>>(We, Wa, n_nodes);
    int warps_ed = (n_edges + 7) / 8;
    k_edge_dot<<<(warps_ed + 7) / 8, 256>>>((const float4*)feats_edge, dst,
                                            n_edges);
    k_gemm<<<(n_nodes + 127) / 128, 256>>>(feats_node, Wn, Wa, n_nodes);
    k_scan<<<1, 1024>>>(n_nodes);
    k_build<<<(n_edges + 255) / 256, 256>>>(src, dst, n_edges);
    k_aggregate<<<(n_nodes + 7) / 8, 256>>>(h, n_nodes);
}

// round 9
// speedup vs baseline: 1.4353x; 1.0055x over previous
#include <cuda_runtime.h>

// ---------------------------------------------------------------------------
// GAT layer, folded + CSR softmax-aggregate (single stream):
//   c      = We^T @ a_e                       (edge GEMM eliminated)
//   edge_dot: vdot_k = feats_edge[k].c  (fully coalesced) + dst histogram
//   gemm   : z = feats_node @ Wn^T  with fused epilogue st[i]=(z.a_src,z.a_dst)
//   scan   : CSR offsets (padded to 1024*20 -> zero-guard, all-register)
//   build  : e = lrelu(vdot + st[src].x + st[dst].y), scatter packed (e,src)
//   aggregate: warp-per-node online-softmax + h = sum alpha*z[src] (L2 gather)
// ---------------------------------------------------------------------------

#define MAX_NODES 20000
#define PAD_NODES 20480   /* 1024 * 20 */
#define MAX_EDGES 640000

__device__ __align__(16) float  g_z[MAX_NODES * 128];
__device__ __align__(8)  float2 g_st[MAX_NODES];
__device__ __align__(16) float  g_c[64];
__device__ float                g_vdot[MAX_EDGES];
__device__ __align__(16) int    g_cnt[PAD_NODES];
__device__ __align__(16) int    g_off[PAD_NODES];
__device__ __align__(16) int    g_cur[PAD_NODES];
__device__ __align__(8) float2  g_pcsr[MAX_EDGES];   // (e, src-as-float-bits)

// -- prep: c = We^T a_e ; zero padded histogram --------------------------------
__global__ void k_prep(const float* __restrict__ We,
                       const float* __restrict__ Wa) {
    int t = blockIdx.x * blockDim.x + threadIdx.x;
    if (t < 64) {
        float acc = 0.f;
#pragma unroll 8
        for (int o = 0; o < 128; o++) acc += We[o * 64 + t] * Wa[256 + o];
        g_c[t] = acc;
    }
    if (t < PAD_NODES) g_cnt[t] = 0;
}

// -- edge feature dot, fully coalesced, 8 edges/warp + fused histogram --------
__global__ __launch_bounds__(256) void k_edge_dot(const float4* __restrict__ fe4,
                                                  const int* __restrict__ dst,
                                                  int n_edges) {
    int w = (blockIdx.x * blockDim.x + threadIdx.x) >> 5;
    int lane = threadIdx.x & 31;
    if (w * 8 >= n_edges) return;
    int total4 = n_edges * 16;
    float4 cc = __ldg((const float4*)g_c + (lane & 15));
    float p[4];
#pragma unroll
    for (int k = 0; k < 4; k++) {
        int idx = w * 128 + k * 32 + lane;
        float4 v = (idx < total4) ? fe4[idx] : make_float4(0.f, 0.f, 0.f, 0.f);
        p[k] = v.x * cc.x + v.y * cc.y + v.z * cc.z + v.w * cc.w;
    }
#pragma unroll
    for (int o = 1; o < 16; o <<= 1) {
#pragma unroll
        for (int k = 0; k < 4; k++)
            p[k] += __shfl_xor_sync(0xFFFFFFFFu, p[k], o);
    }
    if ((lane & 15) == 0) {
        int g = lane >> 4;
#pragma unroll
        for (int k = 0; k < 4; k++) {
            int eid = w * 8 + 2 * k + g;
            if (eid < n_edges) {
                g_vdot[eid] = p[k];
                atomicAdd(&g_cnt[dst[eid]], 1);
            }
        }
    }
}

// -- z = A @ B^T with fused (s,t) epilogue ------------------------------------
__global__ __launch_bounds__(256) void k_gemm(const float* __restrict__ A,
                                              const float* __restrict__ B,
                                              const float* __restrict__ Wa,
                                              int M) {
    __shared__ float As[16][132];
    __shared__ float Bs[16][132];
    const int tid = threadIdx.x;
    const int blockRow = blockIdx.x * 128;
    const int tr = tid >> 4;
    const int tc = tid & 15;
    const int lrow = tid >> 2;
    const int lcol = (tid & 3) * 4;

    float acc[8][8];
#pragma unroll
    for (int i = 0; i < 8; i++)
#pragma unroll
        for (int j = 0; j < 8; j++) acc[i][j] = 0.f;

    for (int kt = 0; kt < 128; kt += 16) {
#pragma unroll
        for (int h = 0; h < 2; h++) {
            int m = lrow + h * 64;
            int gm = blockRow + m;
            float4 v = (gm < M)
                           ? *(const float4*)&A[(size_t)gm * 128 + kt + lcol]
                           : make_float4(0.f, 0.f, 0.f, 0.f);
            As[lcol + 0][m] = v.x; As[lcol + 1][m] = v.y;
            As[lcol + 2][m] = v.z; As[lcol + 3][m] = v.w;
        }
#pragma unroll
        for (int h = 0; h < 2; h++) {
            int n = lrow + h * 64;
            float4 v = *(const float4*)&B[(size_t)n * 128 + kt + lcol];
            Bs[lcol + 0][n] = v.x; Bs[lcol + 1][n] = v.y;
            Bs[lcol + 2][n] = v.z; Bs[lcol + 3][n] = v.w;
        }
        __syncthreads();
#pragma unroll
        for (int k = 0; k < 16; k++) {
            float ra[8], rb[8];
#pragma unroll
            for (int i = 0; i < 8; i++) ra[i] = As[k][tr * 8 + i];
#pragma unroll
            for (int j = 0; j < 8; j++) rb[j] = Bs[k][tc * 8 + j];
#pragma unroll
            for (int i = 0; i < 8; i++)
#pragma unroll
                for (int j = 0; j < 8; j++) acc[i][j] += ra[i] * rb[j];
        }
        __syncthreads();
    }

#pragma unroll
    for (int i = 0; i < 8; i++) {
        int gm = blockRow + tr * 8 + i;
        if (gm < M) {
            float* out = &g_z[(size_t)gm * 128 + tc * 8];
            *(float4*)(out + 0) = make_float4(acc[i][0], acc[i][1], acc[i][2], acc[i][3]);
            *(float4*)(out + 4) = make_float4(acc[i][4], acc[i][5], acc[i][6], acc[i][7]);
        }
    }

    float asv[8], adv[8];
#pragma unroll
    for (int j = 0; j < 8; j++) {
        asv[j] = __ldg(Wa + tc * 8 + j);
        adv[j] = __ldg(Wa + 128 + tc * 8 + j);
    }
#pragma unroll
    for (int i = 0; i < 8; i++) {
        float s = 0.f, t = 0.f;
#pragma unroll
        for (int j = 0; j < 8; j++) {
            s += acc[i][j] * asv[j];
            t += acc[i][j] * adv[j];
        }
#pragma unroll
        for (int o = 1; o < 16; o <<= 1) {
            s += __shfl_xor_sync(0xFFFFFFFFu, s, o);
            t += __shfl_xor_sync(0xFFFFFFFFu, t, o);
        }
        int gm = blockRow + tr * 8 + i;
        if (tc == 0 && gm < M) g_st[gm] = make_float2(s, t);
    }
}

// -- exclusive scan over padded 20480: compile-time C=20, pure registers -------
__global__ __launch_bounds__(1024) void k_scan() {
    __shared__ int wsum[32];
    const int tid = threadIdx.x;
    const int lane = tid & 31, wid = tid >> 5;
    const int lo = tid * 20;

    int vals[20];
#pragma unroll
    for (int k = 0; k < 5; k++) {
        int4 v = *(const int4*)&g_cnt[lo + k * 4];
        vals[k * 4 + 0] = v.x; vals[k * 4 + 1] = v.y;
        vals[k * 4 + 2] = v.z; vals[k * 4 + 3] = v.w;
    }

    int local = 0;
#pragma unroll
    for (int i = 0; i < 20; i++) local += vals[i];

    int v = local;
#pragma unroll
    for (int o = 1; o < 32; o <<= 1) {
        int u = __shfl_up_sync(0xFFFFFFFFu, v, o);
        if (lane >= o) v += u;
    }
    if (lane == 31) wsum[wid] = v;
    __syncthreads();
    if (wid == 0) {
        int wv = wsum[lane];
#pragma unroll
        for (int o = 1; o < 32; o <<= 1) {
            int u = __shfl_up_sync(0xFFFFFFFFu, wv, o);
            if (lane >= o) wv += u;
        }
        wsum[lane] = wv;
    }
    __syncthreads();
    int run = v - local + (wid > 0 ? wsum[wid - 1] : 0);

    int pref[20];
#pragma unroll
    for (int i = 0; i < 20; i++) { pref[i] = run; run += vals[i]; }
#pragma unroll
    for (int k = 0; k < 5; k++) {
        int4 pv = make_int4(pref[k * 4 + 0], pref[k * 4 + 1],
                            pref[k * 4 + 2], pref[k * 4 + 3]);
        *(int4*)&g_off[lo + k * 4] = pv;
        *(int4*)&g_cur[lo + k * 4] = pv;
    }
}

// -- build CSR-ordered packed (e, src), fused logit + leaky-relu ---------------
__global__ void k_build(const int* __restrict__ src,
                        const int* __restrict__ dst, int n_edges) {
    int i = blockIdx.x * blockDim.x + threadIdx.x;
    if (i >= n_edges) return;
    int d = dst[i];
    int s = src[i];
    float logit = g_vdot[i] + g_st[s].x + g_st[d].y;
    float e = (logit > 0.f) ? logit : 0.2f * logit;
    int pos = atomicAdd(&g_cur[d], 1);
    g_pcsr[pos] = make_float2(e, __int_as_float(s));
}

// -- warp per node: online softmax (1 pass) + weighted aggregate, MLP x8 -------
__global__ __launch_bounds__(256) void k_aggregate(float* __restrict__ h,
                                                   int n_nodes) {
    int node = (blockIdx.x * blockDim.x + threadIdx.x) >> 5;
    int lane = threadIdx.x & 31;
    if (node >= n_nodes) return;
    int off = g_off[node];
    int deg = g_cnt[node];

    // online softmax: single coalesced pass for (m, S)
    float m = -3.402823466e+38f;
    float S = 0.f;
    for (int j = lane; j < deg; j += 32) {
        float e = g_pcsr[off + j].x;
        float mn = fmaxf(m, e);
        S = S * __expf(m - mn) + __expf(e - mn);
        m = mn;
    }
#pragma unroll
    for (int o = 16; o > 0; o >>= 1) {
        float mo = __shfl_xor_sync(0xFFFFFFFFu, m, o);
        float So = __shfl_xor_sync(0xFFFFFFFFu, S, o);
        float mn = fmaxf(m, mo);
        S = S * __expf(m - mn) + So * __expf(mo - mn);
        m = mn;
    }
    float rS = (deg > 0) ? (1.f / S) : 0.f;

    float4 accA = make_float4(0.f, 0.f, 0.f, 0.f);
    float4 accB = make_float4(0.f, 0.f, 0.f, 0.f);
    int j = 0;
    for (; j + 8 <= deg; j += 8) {
        float2 p[8];
#pragma unroll
        for (int q = 0; q < 8; q++) p[q] = g_pcsr[off + j + q];
        float4 z[8];
#pragma unroll
        for (int q = 0; q < 8; q++)
            z[q] = *(const float4*)&g_z[(size_t)__float_as_int(p[q].y) * 128 +
                                        lane * 4];
#pragma unroll
        for (int q = 0; q < 8; q++) {
            float a = __expf(p[q].x - m) * rS;
            float4* acc = (q & 1) ? &accB : &accA;
            acc->x += a * z[q].x; acc->y += a * z[q].y;
            acc->z += a * z[q].z; acc->w += a * z[q].w;
        }
    }
    for (; j < deg; j++) {
        float2 p0 = g_pcsr[off + j];
        int s0 = __float_as_int(p0.y);
        float4 z0 = *(const float4*)&g_z[(size_t)s0 * 128 + lane * 4];
        float a0 = __expf(p0.x - m) * rS;
        accA.x += a0 * z0.x; accA.y += a0 * z0.y;
        accA.z += a0 * z0.z; accA.w += a0 * z0.w;
    }
    accA.x += accB.x; accA.y += accB.y; accA.z += accB.z; accA.w += accB.w;
    *(float4*)&h[(size_t)node * 128 + lane * 4] = accA;
}

extern "C" void kernel_launch(void* const* d_in, const int* in_sizes, int n_in,
                              void* d_out, int out_size) {
    const float* feats_node = (const float*)d_in[0];
    const float* feats_edge = (const float*)d_in[1];
    const float* Wn         = (const float*)d_in[2];
    const float* We         = (const float*)d_in[3];
    const float* Wa         = (const float*)d_in[4];
    const int*   src        = (const int*)d_in[5];
    const int*   dst        = (const int*)d_in[6];
    float*       h          = (float*)d_out;

    int n_nodes = in_sizes[0] / 128;
    int n_edges = in_sizes[5];

    k_prep<<<(PAD_NODES + 255) / 256, 256>>>(We, Wa);
    int warps_ed = (n_edges + 7) / 8;
    k_edge_dot<<<(warps_ed + 7) / 8, 256>>>((const float4*)feats_edge, dst,
                                            n_edges);
    k_gemm<<<(n_nodes + 127) / 128, 256>>>(feats_node, Wn, Wa, n_nodes);
    k_scan<<<1, 1024>>>();
    k_build<<<(n_edges + 255) / 256, 256>>>(src, dst, n_edges);
    k_aggregate<<<(n_nodes + 7) / 8, 256>>>(h, n_nodes);
}

// round 10
// speedup vs baseline: 1.6719x; 1.1649x over previous
#include <cuda_runtime.h>
#include <cuda_fp16.h>

// ---------------------------------------------------------------------------
// GAT layer, folded + CSR softmax-aggregate:
//   c      = We^T @ a_e                       (edge GEMM eliminated)
//   edge_dot: vdot_k = feats_edge[k].c  (fully coalesced) + dst histogram
//   gemm   : z = feats_node @ Wn^T, stored fp16; fused st[i]=(z.a_src,z.a_dst)
//   scan   : CSR offsets  (runs CONCURRENT with gemm on a side stream)
//   build  : e = lrelu(vdot + st[src].x + st[dst].y), scatter packed (e,src)
//   aggregate: warp-per-node online-softmax + h = sum alpha*z[src]
//              (fp16 z gather from L2 -> half the traffic, fp32 accumulate)
// ---------------------------------------------------------------------------

#define MAX_NODES 20000
#define PAD_NODES 20480   /* 1024 * 20 */
#define MAX_EDGES 640000

__device__ __align__(16) __half2 g_zh[MAX_NODES * 64];
__device__ __align__(8)  float2  g_st[MAX_NODES];
__device__ __align__(16) float   g_c[64];
__device__ float                 g_vdot[MAX_EDGES];
__device__ __align__(16) int     g_cnt[PAD_NODES];
__device__ __align__(16) int     g_off[PAD_NODES];
__device__ __align__(16) int     g_cur[PAD_NODES];
__device__ __align__(8) float2   g_pcsr[MAX_EDGES];   // (e, src-as-float-bits)

// -- prep: c = We^T a_e ; zero padded histogram --------------------------------
__global__ void k_prep(const float* __restrict__ We,
                       const float* __restrict__ Wa) {
    int t = blockIdx.x * blockDim.x + threadIdx.x;
    if (t < 64) {
        float acc = 0.f;
#pragma unroll 8
        for (int o = 0; o < 128; o++) acc += We[o * 64 + t] * Wa[256 + o];
        g_c[t] = acc;
    }
    if (t < PAD_NODES) g_cnt[t] = 0;
}

// -- edge feature dot, fully coalesced, 8 edges/warp + fused histogram --------
__global__ __launch_bounds__(256) void k_edge_dot(const float4* __restrict__ fe4,
                                                  const int* __restrict__ dst,
                                                  int n_edges) {
    int w = (blockIdx.x * blockDim.x + threadIdx.x) >> 5;
    int lane = threadIdx.x & 31;
    if (w * 8 >= n_edges) return;
    int total4 = n_edges * 16;
    float4 cc = __ldg((const float4*)g_c + (lane & 15));
    float p[4];
#pragma unroll
    for (int k = 0; k < 4; k++) {
        int idx = w * 128 + k * 32 + lane;
        float4 v = (idx < total4) ? fe4[idx] : make_float4(0.f, 0.f, 0.f, 0.f);
        p[k] = v.x * cc.x + v.y * cc.y + v.z * cc.z + v.w * cc.w;
    }
#pragma unroll
    for (int o = 1; o < 16; o <<= 1) {
#pragma unroll
        for (int k = 0; k < 4; k++)
            p[k] += __shfl_xor_sync(0xFFFFFFFFu, p[k], o);
    }
    if ((lane & 15) == 0) {
        int g = lane >> 4;
#pragma unroll
        for (int k = 0; k < 4; k++) {
            int eid = w * 8 + 2 * k + g;
            if (eid < n_edges) {
                g_vdot[eid] = p[k];
                atomicAdd(&g_cnt[dst[eid]], 1);
            }
        }
    }
}

// -- z = A @ B^T with fused (s,t) epilogue; z stored fp16 ----------------------
__global__ __launch_bounds__(256) void k_gemm(const float* __restrict__ A,
                                              const float* __restrict__ B,
                                              const float* __restrict__ Wa,
                                              int M) {
    __shared__ float As[16][132];
    __shared__ float Bs[16][132];
    const int tid = threadIdx.x;
    const int blockRow = blockIdx.x * 128;
    const int tr = tid >> 4;
    const int tc = tid & 15;
    const int lrow = tid >> 2;
    const int lcol = (tid & 3) * 4;

    float acc[8][8];
#pragma unroll
    for (int i = 0; i < 8; i++)
#pragma unroll
        for (int j = 0; j < 8; j++) acc[i][j] = 0.f;

    for (int kt = 0; kt < 128; kt += 16) {
#pragma unroll
        for (int h = 0; h < 2; h++) {
            int m = lrow + h * 64;
            int gm = blockRow + m;
            float4 v = (gm < M)
                           ? *(const float4*)&A[(size_t)gm * 128 + kt + lcol]
                           : make_float4(0.f, 0.f, 0.f, 0.f);
            As[lcol + 0][m] = v.x; As[lcol + 1][m] = v.y;
            As[lcol + 2][m] = v.z; As[lcol + 3][m] = v.w;
        }
#pragma unroll
        for (int h = 0; h < 2; h++) {
            int n = lrow + h * 64;
            float4 v = *(const float4*)&B[(size_t)n * 128 + kt + lcol];
            Bs[lcol + 0][n] = v.x; Bs[lcol + 1][n] = v.y;
            Bs[lcol + 2][n] = v.z; Bs[lcol + 3][n] = v.w;
        }
        __syncthreads();
#pragma unroll
        for (int k = 0; k < 16; k++) {
            float ra[8], rb[8];
#pragma unroll
            for (int i = 0; i < 8; i++) ra[i] = As[k][tr * 8 + i];
#pragma unroll
            for (int j = 0; j < 8; j++) rb[j] = Bs[k][tc * 8 + j];
#pragma unroll
            for (int i = 0; i < 8; i++)
#pragma unroll
                for (int j = 0; j < 8; j++) acc[i][j] += ra[i] * rb[j];
        }
        __syncthreads();
    }

    // store z tile as fp16 (half2 x4 = 16B per thread-row)
#pragma unroll
    for (int i = 0; i < 8; i++) {
        int gm = blockRow + tr * 8 + i;
        if (gm < M) {
            __half2 q[4];
#pragma unroll
            for (int j = 0; j < 4; j++)
                q[j] = __float22half2_rn(
                    make_float2(acc[i][2 * j], acc[i][2 * j + 1]));
            *(uint4*)&g_zh[(size_t)gm * 64 + tc * 4] = *(uint4*)q;
        }
    }

    // fused epilogue: per-row dots with a_src / a_dst (fp32 accs)
    float asv[8], adv[8];
#pragma unroll
    for (int j = 0; j < 8; j++) {
        asv[j] = __ldg(Wa + tc * 8 + j);
        adv[j] = __ldg(Wa + 128 + tc * 8 + j);
    }
#pragma unroll
    for (int i = 0; i < 8; i++) {
        float s = 0.f, t = 0.f;
#pragma unroll
        for (int j = 0; j < 8; j++) {
            s += acc[i][j] * asv[j];
            t += acc[i][j] * adv[j];
        }
#pragma unroll
        for (int o = 1; o < 16; o <<= 1) {
            s += __shfl_xor_sync(0xFFFFFFFFu, s, o);
            t += __shfl_xor_sync(0xFFFFFFFFu, t, o);
        }
        int gm = blockRow + tr * 8 + i;
        if (tc == 0 && gm < M) g_st[gm] = make_float2(s, t);
    }
}

// -- exclusive scan over padded 20480 (overlapped with gemm) -------------------
__global__ __launch_bounds__(1024) void k_scan() {
    __shared__ int wsum[32];
    const int tid = threadIdx.x;
    const int lane = tid & 31, wid = tid >> 5;
    const int lo = tid * 20;

    int vals[20];
#pragma unroll
    for (int k = 0; k < 5; k++) {
        int4 v = *(const int4*)&g_cnt[lo + k * 4];
        vals[k * 4 + 0] = v.x; vals[k * 4 + 1] = v.y;
        vals[k * 4 + 2] = v.z; vals[k * 4 + 3] = v.w;
    }

    int local = 0;
#pragma unroll
    for (int i = 0; i < 20; i++) local += vals[i];

    int v = local;
#pragma unroll
    for (int o = 1; o < 32; o <<= 1) {
        int u = __shfl_up_sync(0xFFFFFFFFu, v, o);
        if (lane >= o) v += u;
    }
    if (lane == 31) wsum[wid] = v;
    __syncthreads();
    if (wid == 0) {
        int wv = wsum[lane];
#pragma unroll
        for (int o = 1; o < 32; o <<= 1) {
            int u = __shfl_up_sync(0xFFFFFFFFu, wv, o);
            if (lane >= o) wv += u;
        }
        wsum[lane] = wv;
    }
    __syncthreads();
    int run = v - local + (wid > 0 ? wsum[wid - 1] : 0);

    int pref[20];
#pragma unroll
    for (int i = 0; i < 20; i++) { pref[i] = run; run += vals[i]; }
#pragma unroll
    for (int k = 0; k < 5; k++) {
        int4 pv = make_int4(pref[k * 4 + 0], pref[k * 4 + 1],
                            pref[k * 4 + 2], pref[k * 4 + 3]);
        *(int4*)&g_off[lo + k * 4] = pv;
        *(int4*)&g_cur[lo + k * 4] = pv;
    }
}

// -- build CSR-ordered packed (e, src), fused logit + leaky-relu ---------------
__global__ void k_build(const int* __restrict__ src,
                        const int* __restrict__ dst, int n_edges) {
    int i = blockIdx.x * blockDim.x + threadIdx.x;
    if (i >= n_edges) return;
    int d = dst[i];
    int s = src[i];
    float logit = g_vdot[i] + g_st[s].x + g_st[d].y;
    float e = (logit > 0.f) ? logit : 0.2f * logit;
    int pos = atomicAdd(&g_cur[d], 1);
    g_pcsr[pos] = make_float2(e, __int_as_float(s));
}

// -- warp per node: online softmax + weighted aggregate over fp16 z ------------
__global__ __launch_bounds__(256) void k_aggregate(float* __restrict__ h,
                                                   int n_nodes) {
    int node = (blockIdx.x * blockDim.x + threadIdx.x) >> 5;
    int lane = threadIdx.x & 31;
    if (node >= n_nodes) return;
    int off = g_off[node];
    int deg = g_cnt[node];

    // online softmax: single coalesced pass for (m, S)
    float m = -3.402823466e+38f;
    float S = 0.f;
    for (int j = lane; j < deg; j += 32) {
        float e = g_pcsr[off + j].x;
        float mn = fmaxf(m, e);
        S = S * __expf(m - mn) + __expf(e - mn);
        m = mn;
    }
#pragma unroll
    for (int o = 16; o > 0; o >>= 1) {
        float mo = __shfl_xor_sync(0xFFFFFFFFu, m, o);
        float So = __shfl_xor_sync(0xFFFFFFFFu, S, o);
        float mn = fmaxf(m, mo);
        S = S * __expf(m - mn) + So * __expf(mo - mn);
        m = mn;
    }
    float rS = (deg > 0) ? (1.f / S) : 0.f;

    float4 accA = make_float4(0.f, 0.f, 0.f, 0.f);
    float4 accB = make_float4(0.f, 0.f, 0.f, 0.f);
    int j = 0;
    for (; j + 8 <= deg; j += 8) {
        float2 p[8];
#pragma unroll
        for (int q = 0; q < 8; q++) p[q] = g_pcsr[off + j + q];
        uint2 zr[8];
#pragma unroll
        for (int q = 0; q < 8; q++)
            zr[q] = *(const uint2*)&g_zh[(size_t)__float_as_int(p[q].y) * 64 +
                                         lane * 2];
#pragma unroll
        for (int q = 0; q < 8; q++) {
            float a = __expf(p[q].x - m) * rS;
            float2 f0 = __half22float2(*(__half2*)&zr[q].x);
            float2 f1 = __half22float2(*(__half2*)&zr[q].y);
            float4* acc = (q & 1) ? &accB : &accA;
            acc->x += a * f0.x; acc->y += a * f0.y;
            acc->z += a * f1.x; acc->w += a * f1.y;
        }
    }
    for (; j < deg; j++) {
        float2 p0 = g_pcsr[off + j];
        uint2 zr = *(const uint2*)&g_zh[(size_t)__float_as_int(p0.y) * 64 +
                                        lane * 2];
        float a0 = __expf(p0.x - m) * rS;
        float2 f0 = __half22float2(*(__half2*)&zr.x);
        float2 f1 = __half22float2(*(__half2*)&zr.y);
        accA.x += a0 * f0.x; accA.y += a0 * f0.y;
        accA.z += a0 * f1.x; accA.w += a0 * f1.y;
    }
    accA.x += accB.x; accA.y += accB.y; accA.z += accB.z; accA.w += accB.w;
    *(float4*)&h[(size_t)node * 128 + lane * 4] = accA;
}

extern "C" void kernel_launch(void* const* d_in, const int* in_sizes, int n_in,
                              void* d_out, int out_size) {
    const float* feats_node = (const float*)d_in[0];
    const float* feats_edge = (const float*)d_in[1];
    const float* Wn         = (const float*)d_in[2];
    const float* We         = (const float*)d_in[3];
    const float* Wa         = (const float*)d_in[4];
    const int*   src        = (const int*)d_in[5];
    const int*   dst        = (const int*)d_in[6];
    float*       h          = (float*)d_out;

    int n_nodes = in_sizes[0] / 128;
    int n_edges = in_sizes[5];

    static cudaStream_t s2 = nullptr;
    static cudaEvent_t evFork = nullptr, evJoin = nullptr;
    if (s2 == nullptr) {
        cudaStreamCreateWithFlags(&s2, cudaStreamNonBlocking);
        cudaEventCreateWithFlags(&evFork, cudaEventDisableTiming);
        cudaEventCreateWithFlags(&evJoin, cudaEventDisableTiming);
    }

    k_prep<<<(PAD_NODES + 255) / 256, 256>>>(We, Wa);
    int warps_ed = (n_edges + 7) / 8;
    k_edge_dot<<<(warps_ed + 7) / 8, 256>>>((const float4*)feats_edge, dst,
                                            n_edges);

    // fork: tiny single-block scan runs concurrently with the compute-bound gemm
    cudaEventRecord(evFork, 0);
    cudaStreamWaitEvent(s2, evFork, 0);
    k_scan<<<1, 1024, 0, s2>>>();
    cudaEventRecord(evJoin, s2);

    k_gemm<<<(n_nodes + 127) / 128, 256>>>(feats_node, Wn, Wa, n_nodes);

    cudaStreamWaitEvent(0, evJoin, 0);
    k_build<<<(n_edges + 255) / 256, 256>>>(src, dst, n_edges);
    k_aggregate<<<(n_nodes + 7) / 8, 256>>>(h, n_nodes);
}